// round 4
// baseline (speedup 1.0000x reference)
#include <cuda_runtime.h>
#include <cstdint>

// ============================================================================
// relu(x @ W^T + b): M=131072, N=256, K=256, fp32.  Base sm_103 target.
// mma.sync.m16n8k8.tf32. CTA 64x256, KC=32, 2-stage.
//  - A staged raw via cp.async; cvt.rna on A fragments in-loop (8/kk).
//  - B staged PRE-CONVERTED via LDG->cvt.rna->STS  => ldmatrix feeds MMA direct.
//  - one __syncthreads per K-chunk.
// ============================================================================

static constexpr int DK = 256;
static constexpr int DN = 256;
static constexpr int BM = 64;
static constexpr int KC = 32;                 // 32 fp32 = 128B row
static constexpr int THREADS = 256;

static constexpr int A_BYTES = BM * KC * 4;   // 8192
static constexpr int B_BYTES = DN * KC * 4;   // 32768
static constexpr int STAGE_BYTES = A_BYTES + B_BYTES;  // 40960
static constexpr int SMEM_DYN = 2 * STAGE_BYTES;       // 81920

// ---------------------------------------------------------------------------
__device__ __forceinline__ uint32_t smem_u32(const void* p) {
    uint32_t a;
    asm("{ .reg .u64 t; cvta.to.shared.u64 t, %1; cvt.u32.u64 %0, t; }" : "=r"(a) : "l"(p));
    return a;
}
__device__ __forceinline__ void cp_async16(uint32_t dst, const void* src) {
    asm volatile("cp.async.cg.shared.global [%0], [%1], 16;" :: "r"(dst), "l"(src));
}
__device__ __forceinline__ void ldsm_x4(uint32_t* d, uint32_t addr) {
    asm volatile("ldmatrix.sync.aligned.m8n8.x4.shared.b16 {%0,%1,%2,%3}, [%4];"
                 : "=r"(d[0]), "=r"(d[1]), "=r"(d[2]), "=r"(d[3]) : "r"(addr));
}
__device__ __forceinline__ uint32_t tf32r(float v) {
    uint32_t r;
    asm("cvt.rna.tf32.f32 %0, %1;" : "=r"(r) : "f"(v));
    return r;
}
__device__ __forceinline__ uint32_t tf32u(uint32_t v) {
    uint32_t r;
    asm("cvt.rna.tf32.f32 %0, %1;" : "=r"(r) : "f"(__uint_as_float(v)));
    return r;
}
__device__ __forceinline__ void mma_tf32(float* d, const uint32_t* a,
                                         uint32_t b0, uint32_t b1) {
    asm volatile(
        "mma.sync.aligned.m16n8k8.row.col.f32.tf32.tf32.f32 "
        "{%0,%1,%2,%3}, {%4,%5,%6,%7}, {%8,%9}, {%0,%1,%2,%3};"
        : "+f"(d[0]), "+f"(d[1]), "+f"(d[2]), "+f"(d[3])
        : "r"(a[0]), "r"(a[1]), "r"(a[2]), "r"(a[3]), "r"(b0), "r"(b1));
}
__device__ __forceinline__ void sts_tf32x4(uint32_t dst, float4 v) {
    uint32_t w0 = tf32r(v.x), w1 = tf32r(v.y), w2 = tf32r(v.z), w3 = tf32r(v.w);
    asm volatile("st.shared.v4.b32 [%0], {%1, %2, %3, %4};"
                 :: "r"(dst), "r"(w0), "r"(w1), "r"(w2), "r"(w3) : "memory");
}

// swizzled byte offset within a (rows x 32 fp32) tile
__device__ __forceinline__ uint32_t swz(int row, int seg) {
    return (uint32_t)row * 128u + (uint32_t)((seg * 16) ^ ((row & 7) * 16));
}

// ---------------------------------------------------------------------------
__global__ __launch_bounds__(THREADS, 2)
void gemm_relu_tf32_kernel(const float* __restrict__ x, const float* __restrict__ W,
                           const float* __restrict__ bias, float* __restrict__ out) {
    extern __shared__ __align__(1024) char smem_raw[];
    const uint32_t base = smem_u32(smem_raw);

    const int tid = threadIdx.x;
    const int wid = tid >> 5;
    const int lid = tid & 31;
    const int g   = lid >> 2;
    const int t   = lid & 3;
    const int wm  = wid & 1;       // warp m-tile (2 x 32 rows)
    const int wn  = wid >> 1;      // warp n-tile (4 x 64 cols)
    const int m0  = blockIdx.x * BM;

    // ldmatrix lane role
    const int mx = lid >> 3;
    const int r  = lid & 7;
    const uint32_t xr = (uint32_t)(r * 16);

    uint32_t a_row[2], b_row[4];
    #pragma unroll
    for (int mt = 0; mt < 2; mt++)
        a_row[mt] = (uint32_t)(wm * 32 + mt * 16 + (mx & 1) * 8 + r) * 128u;
    #pragma unroll
    for (int ntp = 0; ntp < 4; ntp++)
        b_row[ntp] = (uint32_t)(wn * 64 + ntp * 16 + (mx >> 1) * 8 + r) * 128u;
    const uint32_t a_sel = (uint32_t)((mx >> 1) * 16);
    const uint32_t b_sel = (uint32_t)((mx & 1) * 16);

    // per-thread load roles (A: 2 float4; B: 8 float4 in two halves)
    const int lrow = tid >> 3;       // 0..31
    const int lseg = tid & 7;        // 0..7

    // ---- prologue: stage chunk 0
    {
        // A0 via cp.async (raw fp32)
        #pragma unroll
        for (int i = 0; i < 2; i++) {
            int row = i * 32 + lrow;
            cp_async16(base + swz(row, lseg),
                       x + (size_t)(m0 + row) * DK + lseg * 4);
        }
        asm volatile("cp.async.commit_group;" ::: "memory");
        // B0 via LDG -> cvt -> STS
        #pragma unroll
        for (int i = 0; i < 8; i++) {
            int row = i * 32 + lrow;
            float4 v = *reinterpret_cast<const float4*>(W + (size_t)row * DK + lseg * 4);
            sts_tf32x4(base + A_BYTES + swz(row, lseg), v);
        }
    }

    float acc[2][8][4];
    #pragma unroll
    for (int mt = 0; mt < 2; mt++)
        #pragma unroll
        for (int nt = 0; nt < 8; nt++)
            #pragma unroll
            for (int j = 0; j < 4; j++) acc[mt][nt][j] = 0.0f;

    #pragma unroll
    for (int kc = 0; kc < 8; kc++) {
        asm volatile("cp.async.wait_group 0;" ::: "memory");
        __syncthreads();

        const uint32_t As = base + (uint32_t)(kc & 1) * STAGE_BYTES;
        const uint32_t Bs = As + A_BYTES;
        const uint32_t Ad = base + (uint32_t)((kc + 1) & 1) * STAGE_BYTES;
        const uint32_t Bd = Ad + A_BYTES;
        const int k1 = (kc + 1) * KC;

        float4 buf[4];
        if (kc < 7) {
            #pragma unroll
            for (int i = 0; i < 2; i++) {
                int row = i * 32 + lrow;
                cp_async16(Ad + swz(row, lseg),
                           x + (size_t)(m0 + row) * DK + k1 + lseg * 4);
            }
            asm volatile("cp.async.commit_group;" ::: "memory");
            #pragma unroll
            for (int i = 0; i < 4; i++) {
                int row = i * 32 + lrow;
                buf[i] = *reinterpret_cast<const float4*>(W + (size_t)row * DK + k1 + lseg * 4);
            }
        }

        // kk 0,1
        #pragma unroll
        for (int kk = 0; kk < 2; kk++) {
            const uint32_t acol = ((uint32_t)(kk * 32) + a_sel) ^ xr;
            const uint32_t bcol = ((uint32_t)(kk * 32) + b_sel) ^ xr;
            uint32_t a[2][4];
            #pragma unroll
            for (int mt = 0; mt < 2; mt++) {
                ldsm_x4(a[mt], As + a_row[mt] + acol);
                #pragma unroll
                for (int j = 0; j < 4; j++) a[mt][j] = tf32u(a[mt][j]);
            }
            uint32_t bb[4][4];
            #pragma unroll
            for (int ntp = 0; ntp < 4; ntp++)
                ldsm_x4(bb[ntp], Bs + b_row[ntp] + bcol);
            #pragma unroll
            for (int ntp = 0; ntp < 4; ntp++) {
                mma_tf32(acc[0][2 * ntp],     a[0], bb[ntp][0], bb[ntp][1]);
                mma_tf32(acc[1][2 * ntp],     a[1], bb[ntp][0], bb[ntp][1]);
                mma_tf32(acc[0][2 * ntp + 1], a[0], bb[ntp][2], bb[ntp][3]);
                mma_tf32(acc[1][2 * ntp + 1], a[1], bb[ntp][2], bb[ntp][3]);
            }
        }

        if (kc < 7) {
            #pragma unroll
            for (int i = 0; i < 4; i++) {
                int row = i * 32 + lrow;
                sts_tf32x4(Bd + swz(row, lseg), buf[i]);
            }
            #pragma unroll
            for (int i = 0; i < 4; i++) {
                int row = (i + 4) * 32 + lrow;
                buf[i] = *reinterpret_cast<const float4*>(W + (size_t)row * DK + k1 + lseg * 4);
            }
        }

        // kk 2,3
        #pragma unroll
        for (int kk = 2; kk < 4; kk++) {
            const uint32_t acol = ((uint32_t)(kk * 32) + a_sel) ^ xr;
            const uint32_t bcol = ((uint32_t)(kk * 32) + b_sel) ^ xr;
            uint32_t a[2][4];
            #pragma unroll
            for (int mt = 0; mt < 2; mt++) {
                ldsm_x4(a[mt], As + a_row[mt] + acol);
                #pragma unroll
                for (int j = 0; j < 4; j++) a[mt][j] = tf32u(a[mt][j]);
            }
            uint32_t bb[4][4];
            #pragma unroll
            for (int ntp = 0; ntp < 4; ntp++)
                ldsm_x4(bb[ntp], Bs + b_row[ntp] + bcol);
            #pragma unroll
            for (int ntp = 0; ntp < 4; ntp++) {
                mma_tf32(acc[0][2 * ntp],     a[0], bb[ntp][0], bb[ntp][1]);
                mma_tf32(acc[1][2 * ntp],     a[1], bb[ntp][0], bb[ntp][1]);
                mma_tf32(acc[0][2 * ntp + 1], a[0], bb[ntp][2], bb[ntp][3]);
                mma_tf32(acc[1][2 * ntp + 1], a[1], bb[ntp][2], bb[ntp][3]);
            }
        }

        if (kc < 7) {
            #pragma unroll
            for (int i = 0; i < 4; i++) {
                int row = (i + 4) * 32 + lrow;
                sts_tf32x4(Bd + swz(row, lseg), buf[i]);
            }
        }
    }

    // ---- epilogue: bias + relu, float2 stores
    const int m_base = m0 + wm * 32;
    const int n_base = wn * 64;
    #pragma unroll
    for (int nt = 0; nt < 8; nt++) {
        const int col = n_base + nt * 8 + 2 * t;
        const float2 bv = *reinterpret_cast<const float2*>(bias + col);
        #pragma unroll
        for (int mt = 0; mt < 2; mt++) {
            const int row0 = m_base + mt * 16 + g;
            float2 v0;
            v0.x = fmaxf(acc[mt][nt][0] + bv.x, 0.0f);
            v0.y = fmaxf(acc[mt][nt][1] + bv.y, 0.0f);
            *reinterpret_cast<float2*>(out + (size_t)row0 * DN + col) = v0;
            float2 v1;
            v1.x = fmaxf(acc[mt][nt][2] + bv.x, 0.0f);
            v1.y = fmaxf(acc[mt][nt][3] + bv.y, 0.0f);
            *reinterpret_cast<float2*>(out + (size_t)(row0 + 8) * DN + col) = v1;
        }
    }
}

// ---------------------------------------------------------------------------
extern "C" void kernel_launch(void* const* d_in, const int* in_sizes, int n_in,
                              void* d_out, int out_size) {
    const float* x = (const float*)d_in[0];
    const float* W = (const float*)d_in[1];
    const float* b = (const float*)d_in[2];
    float* out = (float*)d_out;

    int Brows = in_sizes[0] / DK;     // 131072
    int grid  = Brows / BM;           // 2048

    cudaFuncSetAttribute(gemm_relu_tf32_kernel,
                         cudaFuncAttributeMaxDynamicSharedMemorySize, SMEM_DYN);
    gemm_relu_tf32_kernel<<<grid, THREADS, SMEM_DYN>>>(x, W, b, out);
}

// round 5
// speedup vs baseline: 1.2142x; 1.2142x over previous
#include <cuda_runtime.h>
#include <cstdint>

// ============================================================================
// relu(x @ W^T + b): M=131072, N=256, K=256, fp32.  Base sm_103 target.
// mma.sync.m16n8k8.tf32. CTA 64x256, KC=32, 2-stage cp.async, 1 barrier/chunk.
//  - W pre-converted to tf32(RNA) once into __device__ scratch (256KB, ~2us)
//    -> B path is cp.async raw bits, ldmatrix feeds MMA with ZERO in-loop cvt.
//  - A staged raw via cp.async; cvt.rna on A fragments in-loop (8 regs/kk).
// ============================================================================

static constexpr int DK = 256;
static constexpr int DN = 256;
static constexpr int BM = 64;
static constexpr int KC = 32;                 // 32 fp32 = 128B row
static constexpr int THREADS = 256;

static constexpr int A_BYTES = BM * KC * 4;   // 8192
static constexpr int B_BYTES = DN * KC * 4;   // 32768
static constexpr int STAGE_BYTES = A_BYTES + B_BYTES;  // 40960
static constexpr int SMEM_DYN = 2 * STAGE_BYTES;       // 81920

__device__ float W_cvt[DN * DK];              // 256KB static scratch (tf32 bits)

// ---------------------------------------------------------------------------
__device__ __forceinline__ uint32_t smem_u32(const void* p) {
    uint32_t a;
    asm("{ .reg .u64 t; cvta.to.shared.u64 t, %1; cvt.u32.u64 %0, t; }" : "=r"(a) : "l"(p));
    return a;
}
__device__ __forceinline__ void cp_async16(uint32_t dst, const void* src) {
    asm volatile("cp.async.cg.shared.global [%0], [%1], 16;" :: "r"(dst), "l"(src));
}
__device__ __forceinline__ void ldsm_x4(uint32_t* d, uint32_t addr) {
    asm volatile("ldmatrix.sync.aligned.m8n8.x4.shared.b16 {%0,%1,%2,%3}, [%4];"
                 : "=r"(d[0]), "=r"(d[1]), "=r"(d[2]), "=r"(d[3]) : "r"(addr));
}
__device__ __forceinline__ uint32_t tf32r(float v) {
    uint32_t r;
    asm("cvt.rna.tf32.f32 %0, %1;" : "=r"(r) : "f"(v));
    return r;
}
__device__ __forceinline__ uint32_t tf32u(uint32_t v) {
    uint32_t r;
    asm("cvt.rna.tf32.f32 %0, %1;" : "=r"(r) : "f"(__uint_as_float(v)));
    return r;
}
__device__ __forceinline__ void mma_tf32(float* d, const uint32_t* a,
                                         uint32_t b0, uint32_t b1) {
    asm volatile(
        "mma.sync.aligned.m16n8k8.row.col.f32.tf32.tf32.f32 "
        "{%0,%1,%2,%3}, {%4,%5,%6,%7}, {%8,%9}, {%0,%1,%2,%3};"
        : "+f"(d[0]), "+f"(d[1]), "+f"(d[2]), "+f"(d[3])
        : "r"(a[0]), "r"(a[1]), "r"(a[2]), "r"(a[3]), "r"(b0), "r"(b1));
}
// swizzled byte offset within a (rows x 32 fp32) tile
__device__ __forceinline__ uint32_t swz(int row, int seg) {
    return (uint32_t)row * 128u + (uint32_t)((seg * 16) ^ ((row & 7) * 16));
}

// ---------------------------------------------------------------------------
// pre-pass: W -> tf32(RNA) bits, 16384 float4
__global__ void convert_W_kernel(const float* __restrict__ W) {
    int i = blockIdx.x * 256 + threadIdx.x;
    float4 v = reinterpret_cast<const float4*>(W)[i];
    float4 o;
    o.x = __uint_as_float(tf32r(v.x));
    o.y = __uint_as_float(tf32r(v.y));
    o.z = __uint_as_float(tf32r(v.z));
    o.w = __uint_as_float(tf32r(v.w));
    reinterpret_cast<float4*>(W_cvt)[i] = o;
}

// ---------------------------------------------------------------------------
__global__ __launch_bounds__(THREADS, 2)
void gemm_relu_tf32_kernel(const float* __restrict__ x,
                           const float* __restrict__ bias, float* __restrict__ out) {
    extern __shared__ __align__(1024) char smem_raw[];
    const uint32_t base = smem_u32(smem_raw);

    const int tid = threadIdx.x;
    const int wid = tid >> 5;
    const int lid = tid & 31;
    const int g   = lid >> 2;
    const int t   = lid & 3;
    const int wm  = wid & 1;       // warp m-tile (2 x 32 rows)
    const int wn  = wid >> 1;      // warp n-tile (4 x 64 cols)
    const int m0  = blockIdx.x * BM;

    // ldmatrix lane role
    const int mx = lid >> 3;
    const int r  = lid & 7;
    const uint32_t xr = (uint32_t)(r * 16);

    uint32_t a_row[2], b_row[4];
    #pragma unroll
    for (int mt = 0; mt < 2; mt++)
        a_row[mt] = (uint32_t)(wm * 32 + mt * 16 + (mx & 1) * 8 + r) * 128u;
    #pragma unroll
    for (int ntp = 0; ntp < 4; ntp++)
        b_row[ntp] = (uint32_t)(wn * 64 + ntp * 16 + (mx >> 1) * 8 + r) * 128u;
    const uint32_t a_sel = (uint32_t)((mx >> 1) * 16);
    const uint32_t b_sel = (uint32_t)((mx & 1) * 16);

    // load roles: A 2 float4/thread, B 8 float4/thread
    const int lrow = tid >> 3;       // 0..31
    const int lseg = tid & 7;        // 0..7

    // ---- prologue: stage chunk 0 into stage 0
    #pragma unroll
    for (int i = 0; i < 2; i++) {
        int row = i * 32 + lrow;
        cp_async16(base + swz(row, lseg), x + (size_t)(m0 + row) * DK + lseg * 4);
    }
    #pragma unroll
    for (int i = 0; i < 8; i++) {
        int row = i * 32 + lrow;
        cp_async16(base + A_BYTES + swz(row, lseg), W_cvt + (size_t)row * DK + lseg * 4);
    }
    asm volatile("cp.async.commit_group;" ::: "memory");

    float acc[2][8][4];
    #pragma unroll
    for (int mt = 0; mt < 2; mt++)
        #pragma unroll
        for (int nt = 0; nt < 8; nt++)
            #pragma unroll
            for (int j = 0; j < 4; j++) acc[mt][nt][j] = 0.0f;

    #pragma unroll
    for (int kc = 0; kc < 8; kc++) {
        asm volatile("cp.async.wait_group 0;" ::: "memory");
        __syncthreads();
        // stage (kc+1)&1 held chunk kc-1; all its readers passed the barrier.

        const uint32_t As = base + (uint32_t)(kc & 1) * STAGE_BYTES;
        const uint32_t Bs = As + A_BYTES;

        if (kc < 7) {
            const uint32_t Ad = base + (uint32_t)((kc + 1) & 1) * STAGE_BYTES;
            const uint32_t Bd = Ad + A_BYTES;
            const int k1 = (kc + 1) * KC;
            #pragma unroll
            for (int i = 0; i < 2; i++) {
                int row = i * 32 + lrow;
                cp_async16(Ad + swz(row, lseg),
                           x + (size_t)(m0 + row) * DK + k1 + lseg * 4);
            }
            #pragma unroll
            for (int i = 0; i < 8; i++) {
                int row = i * 32 + lrow;
                cp_async16(Bd + swz(row, lseg), W_cvt + (size_t)row * DK + k1 + lseg * 4);
            }
            asm volatile("cp.async.commit_group;" ::: "memory");
        }

        #pragma unroll
        for (int kk = 0; kk < 4; kk++) {
            const uint32_t acol = ((uint32_t)(kk * 32) + a_sel) ^ xr;
            const uint32_t bcol = ((uint32_t)(kk * 32) + b_sel) ^ xr;

            uint32_t a[2][4];
            #pragma unroll
            for (int mt = 0; mt < 2; mt++) {
                ldsm_x4(a[mt], As + a_row[mt] + acol);
                #pragma unroll
                for (int j = 0; j < 4; j++) a[mt][j] = tf32u(a[mt][j]);
            }
            uint32_t bb[4][4];
            #pragma unroll
            for (int ntp = 0; ntp < 4; ntp++)
                ldsm_x4(bb[ntp], Bs + b_row[ntp] + bcol);    // already tf32 bits
            #pragma unroll
            for (int ntp = 0; ntp < 4; ntp++) {
                mma_tf32(acc[0][2 * ntp],     a[0], bb[ntp][0], bb[ntp][1]);
                mma_tf32(acc[1][2 * ntp],     a[1], bb[ntp][0], bb[ntp][1]);
                mma_tf32(acc[0][2 * ntp + 1], a[0], bb[ntp][2], bb[ntp][3]);
                mma_tf32(acc[1][2 * ntp + 1], a[1], bb[ntp][2], bb[ntp][3]);
            }
        }
    }

    // ---- epilogue: bias + relu, float2 stores
    const int m_base = m0 + wm * 32;
    const int n_base = wn * 64;
    #pragma unroll
    for (int nt = 0; nt < 8; nt++) {
        const int col = n_base + nt * 8 + 2 * t;
        const float2 bv = *reinterpret_cast<const float2*>(bias + col);
        #pragma unroll
        for (int mt = 0; mt < 2; mt++) {
            const int row0 = m_base + mt * 16 + g;
            float2 v0;
            v0.x = fmaxf(acc[mt][nt][0] + bv.x, 0.0f);
            v0.y = fmaxf(acc[mt][nt][1] + bv.y, 0.0f);
            *reinterpret_cast<float2*>(out + (size_t)row0 * DN + col) = v0;
            float2 v1;
            v1.x = fmaxf(acc[mt][nt][2] + bv.x, 0.0f);
            v1.y = fmaxf(acc[mt][nt][3] + bv.y, 0.0f);
            *reinterpret_cast<float2*>(out + (size_t)(row0 + 8) * DN + col) = v1;
        }
    }
}

// ---------------------------------------------------------------------------
extern "C" void kernel_launch(void* const* d_in, const int* in_sizes, int n_in,
                              void* d_out, int out_size) {
    const float* x = (const float*)d_in[0];
    const float* W = (const float*)d_in[1];
    const float* b = (const float*)d_in[2];
    float* out = (float*)d_out;

    int Brows = in_sizes[0] / DK;     // 131072
    int grid  = Brows / BM;           // 2048

    convert_W_kernel<<<DN * DK / 4 / 256, 256>>>(W);   // 64 blocks

    cudaFuncSetAttribute(gemm_relu_tf32_kernel,
                         cudaFuncAttributeMaxDynamicSharedMemorySize, SMEM_DYN);
    gemm_relu_tf32_kernel<<<grid, THREADS, SMEM_DYN>>>(x, b, out);
}